// round 7
// baseline (speedup 1.0000x reference)
#include <cuda_runtime.h>
#include <cstdint>

#define HH 19
#define CELLS 361
#define MASK19 0x7FFFFu
#define BPB 8
#define NT 640                // 20 warps
#define NWARP 20
#define NBITW 201             // ballot words (max idx 199) + funnel pad
#define FULLM 0xFFFFFFFFu

// weak = opp stone with exactly one orthogonal opp neighbor
__device__ __forceinline__ uint32_t weak_row(uint32_t om, uint32_t ou, uint32_t od) {
    const uint32_t ol  = (om << 1) & MASK19;
    const uint32_t orr = om >> 1;
    const uint32_t par = ou ^ od ^ ol ^ orr;
    const uint32_t ge2 = (ou & od) | (ol & orr) | ((ou | od) & (ol | orr));
    return om & par & ~ge2;
}

// aligned 32-bit word w (bits [32w,32w+32)) of the 361-bit stream of 19 row masks
__device__ __forceinline__ uint32_t gather_word(const uint32_t* rm, int w) {
    uint32_t v = 0u;
    int r = (32 * w) / HH;
#pragma unroll
    for (int it = 0; it < 3; ++it) {
        if (r < HH) {
            const int sh = HH * r - 32 * w;
            if (sh < 32) {
                v |= (sh >= 0) ? (rm[r] << sh) : (rm[r] >> (-sh));
                ++r;
            }
        }
    }
    return v;
}

// 4 bits -> 4 bytes (0/1) at byte lanes 0..3
__device__ __forceinline__ uint32_t spread4(uint32_t nib) {
    return (nib * 0x00204081u) & 0x01010101u;
}

__global__ __launch_bounds__(NT)
void go_feat_kernel(const float* __restrict__ stones,
                    const int*   __restrict__ cur_player,
                    const int*   __restrict__ ko_points,
                    float*       __restrict__ out,
                    int B)
{
    __shared__ uint32_t s_bits[NBITW];        // input bitstream (8 boards * 722 bits)
    __shared__ uint32_t s_cur[BPB][23];       // pad-2 row masks (real rows at [2..20])
    __shared__ uint32_t s_opp[BPB][23];
    __shared__ uint32_t s_emp[BPB][23];
    __shared__ uint32_t s_rm[4][BPB][HH];     // 0=legal, 1=b0, 2=b1, 3=b2
    __shared__ int      s_cp[BPB];
    __shared__ float    s_turn[BPB];
    __shared__ int      s_ko[BPB][2];

    const int t     = threadIdx.x;
    const int bbase = blockIdx.x * BPB;
    const int rb    = (B - bbase) < BPB ? (B - bbase) : BPB;
    const int nin   = rb * 722;

    if (t < BPB) {
        const bool ok = t < rb;
        const int  b  = bbase + (ok ? t : 0);
        const int  cp = ok ? cur_player[b] : 0;
        s_cp[t]    = cp;
        s_turn[t]  = (float)cp;
        s_ko[t][0] = ok ? ko_points[2 * b]     : -1;
        s_ko[t][1] = ok ? ko_points[2 * b + 1] : 0;
    }

    // ---- Phase A: ballot-pack input into bitstream ----
    const float* src = stones + (size_t)bbase * 722;
#pragma unroll
    for (int k = 0; k < 10; ++k) {            // 10*640 = 6400 >= 5776
        const int i = k * NT + t;
        const bool act = i < nin;
        float v = 0.0f;
        if (act) v = src[i];
        const unsigned bal = __ballot_sync(FULLM, act && (v > 0.5f));
        if ((t & 31) == 0)
            s_bits[k * NWARP + (t >> 5)] = bal;
    }
    __syncthreads();

    // ---- Phase 1: row masks ----
    if (t < BPB * HH) {
        const int lb = t / HH, r = t % HH;
        const int bit0 = lb * 722 + r * HH;
        const int bit1 = bit0 + 361;
        const uint32_t m0 = __funnelshift_r(s_bits[bit0 >> 5], s_bits[(bit0 >> 5) + 1],
                                            bit0 & 31) & MASK19;
        const uint32_t m1 = __funnelshift_r(s_bits[bit1 >> 5], s_bits[(bit1 >> 5) + 1],
                                            bit1 & 31) & MASK19;
        const int cp = s_cp[lb];
        s_cur[lb][r + 2] = cp ? m1 : m0;
        s_opp[lb][r + 2] = cp ? m0 : m1;
        s_emp[lb][r + 2] = (~(m0 | m1)) & MASK19;
        if (r == 0) {
            s_cur[lb][0] = 0u; s_cur[lb][1] = 0u; s_cur[lb][21] = 0u; s_cur[lb][22] = 0u;
            s_opp[lb][0] = 0u; s_opp[lb][1] = 0u; s_opp[lb][21] = 0u; s_opp[lb][22] = 0u;
            s_emp[lb][0] = 0u; s_emp[lb][1] = 0u; s_emp[lb][21] = 0u; s_emp[lb][22] = 0u;
        }
    }
    __syncthreads();

    // ---- Phase 3: legal row masks (weak inlined) + liberty bitplanes ----
    if (t < 2 * BPB * HH) {
        const int half = t / (BPB * HH);
        const int w    = t % (BPB * HH);
        const int lb   = w / HH, r = w % HH;
        if (half == 0) {
            const uint32_t* op = s_opp[lb];
            const uint32_t wkm = weak_row(op[r + 2], op[r + 1], op[r + 3]);
            const uint32_t wku = weak_row(op[r + 1], op[r],     op[r + 2]);
            const uint32_t wkd = weak_row(op[r + 3], op[r + 2], op[r + 4]);
            const uint32_t empb = s_emp[lb][r + 2];
            const uint32_t eu = s_emp[lb][r + 1], ed = s_emp[lb][r + 3];
            const uint32_t nbr = eu | ed | ((empb << 1) & MASK19) | (empb >> 1)
                               | wku | wkd | ((wkm << 1) & MASK19) | (wkm >> 1);
            uint32_t legal = empb & nbr;
            const int kr = s_ko[lb][0];
            if (kr >= 0) {
                const int rr = kr > (HH - 1) ? (HH - 1) : kr;
                int cc = s_ko[lb][1];
                cc = cc < 0 ? 0 : (cc > (HH - 1) ? (HH - 1) : cc);
                if (rr == r) legal &= ~(1u << cc);
            }
            s_rm[0][lb][r] = legal;
        } else {
            const uint32_t curb = s_cur[lb][r + 2];
            const uint32_t cu   = s_cur[lb][r + 1];
            const uint32_t cd   = s_cur[lb][r + 3];
            const uint32_t cl   = (curb << 1) & MASK19;
            const uint32_t crr  = curb >> 1;
            const uint32_t empb = s_emp[lb][r + 2];
            const uint32_t sab = cu ^ cd,  cab = cu & cd;
            const uint32_t scd = cl ^ crr, ccd = cl & crr;
            const uint32_t kk  = sab & scd;
            s_rm[1][lb][r] = (sab ^ scd)      & empb;
            s_rm[2][lb][r] = (cab ^ ccd ^ kk) & empb;
            s_rm[3][lb][r] = (cab & ccd)      & empb;
        }
    }
    __syncthreads();

    // ---- Phase 4: warp-per-(board,channel), aligned float4 expansion ----
    const int warp = t >> 5, lane = t & 31;
    float* outb = out + (size_t)bbase * 1805;          // 16B-aligned (8*1805 % 4 == 0)

#pragma unroll
    for (int u = warp; u < 5 * BPB; u += NWARP) {      // 2 units per warp
        const int lb = u / 5;
        const int ch = u - 5 * lb;
        if (lb >= rb) continue;

        const int Grel  = lb * 1805 + ch * CELLS;
        float* o        = outb + Grel;
        const int s     = (4 - (Grel & 3)) & 3;        // head scalars
        const int ng    = (CELLS - s) >> 2;            // aligned float4 groups
        const int tbase = s + 4 * ng;
        const int tcnt  = CELLS - tbase;               // tail scalars (word 11 bits)
        float4* o4      = (float4*)(o + s);

        if (ch == 4) {
            const float tv = s_turn[lb];
            if (lane < s)    o[lane] = tv;
            if (lane < tcnt) o[tbase + lane] = tv;
            const float4 v = make_float4(tv, tv, tv, tv);
#pragma unroll
            for (int it = 0; it < 3; ++it) {
                const int j = it * 32 + lane;
                if (j < ng) o4[j] = v;
            }
        } else if (ch == 3) {
            uint32_t w0 = 0u, w1 = 0u, w2 = 0u;
            if (lane < 12) {
                w0 = gather_word(s_rm[1][lb], lane);
                w1 = gather_word(s_rm[2][lb], lane);
                w2 = gather_word(s_rm[3][lb], lane);
            }
            const uint32_t h0 = __shfl_sync(FULLM, w0, 0);
            const uint32_t h1 = __shfl_sync(FULLM, w1, 0);
            const uint32_t h2 = __shfl_sync(FULLM, w2, 0);
            const uint32_t e0 = __shfl_sync(FULLM, w0, 11);
            const uint32_t e1 = __shfl_sync(FULLM, w1, 11);
            const uint32_t e2 = __shfl_sync(FULLM, w2, 11);
            if (lane < s) {
                const uint32_t n = ((h0 >> lane) & 1u) | (((h1 >> lane) & 1u) << 1)
                                 | (((h2 >> lane) & 1u) << 2);
                o[lane] = (float)n;
            }
            if (lane < tcnt) {
                const int sh = tbase + lane - 352;
                const uint32_t n = ((e0 >> sh) & 1u) | (((e1 >> sh) & 1u) << 1)
                                 | (((e2 >> sh) & 1u) << 2);
                o[tbase + lane] = (float)n;
            }
#pragma unroll
            for (int it = 0; it < 3; ++it) {
                const int j  = it * 32 + lane;
                const int bp = s + 4 * j;
                const int q  = bp >> 5, sh = bp & 31;
                const uint32_t alo = __shfl_sync(FULLM, w0, q);
                const uint32_t ahi = __shfl_sync(FULLM, w0, q + 1);
                const uint32_t blo = __shfl_sync(FULLM, w1, q);
                const uint32_t bhi = __shfl_sync(FULLM, w1, q + 1);
                const uint32_t clo = __shfl_sync(FULLM, w2, q);
                const uint32_t chi = __shfl_sync(FULLM, w2, q + 1);
                const uint32_t n0 = __funnelshift_r(alo, ahi, sh) & 0xFu;
                const uint32_t n1 = __funnelshift_r(blo, bhi, sh) & 0xFu;
                const uint32_t n2 = __funnelshift_r(clo, chi, sh) & 0xFu;
                const uint32_t m = spread4(n0) + (spread4(n1) << 1) + (spread4(n2) << 2);
                float4 v;
                v.x = (float)__byte_perm(m, 0u, 0x4440);
                v.y = (float)__byte_perm(m, 0u, 0x4441);
                v.z = (float)__byte_perm(m, 0u, 0x4442);
                v.w = (float)__byte_perm(m, 0u, 0x4443);
                if (j < ng) o4[j] = v;
            }
        } else {
            uint32_t myw = 0u;
            if (lane < 12) {
                if (ch == 2) {
                    myw = gather_word(s_rm[0][lb], lane);
                } else {
                    const int pl   = (ch == 0) ? s_cp[lb] : 1 - s_cp[lb];
                    const int base = lb * 722 + pl * CELLS + 32 * lane;
                    myw = __funnelshift_r(s_bits[base >> 5], s_bits[(base >> 5) + 1],
                                          base & 31);
                    if (lane == 11) myw &= 0x1FFu;     // drop bits past cell 360
                }
            }
            const uint32_t h = __shfl_sync(FULLM, myw, 0);
            const uint32_t e = __shfl_sync(FULLM, myw, 11);
            if (lane < s)    o[lane] = (float)((h >> lane) & 1u);
            if (lane < tcnt) o[tbase + lane] = (float)((e >> (tbase + lane - 352)) & 1u);
#pragma unroll
            for (int it = 0; it < 3; ++it) {
                const int j  = it * 32 + lane;
                const int bp = s + 4 * j;
                const int q  = bp >> 5, sh = bp & 31;
                const uint32_t lo  = __shfl_sync(FULLM, myw, q);
                const uint32_t hi  = __shfl_sync(FULLM, myw, q + 1);
                const uint32_t nib = __funnelshift_r(lo, hi, sh) & 0xFu;
                const uint32_t m   = spread4(nib);
                float4 v;
                v.x = (float)__byte_perm(m, 0u, 0x4440);
                v.y = (float)__byte_perm(m, 0u, 0x4441);
                v.z = (float)__byte_perm(m, 0u, 0x4442);
                v.w = (float)__byte_perm(m, 0u, 0x4443);
                if (j < ng) o4[j] = v;
            }
        }
    }
}

extern "C" void kernel_launch(void* const* d_in, const int* in_sizes, int n_in,
                              void* d_out, int out_size)
{
    const float* stones     = (const float*)d_in[0];
    const int*   cur_player = (const int*)  d_in[1];
    const int*   ko_points  = (const int*)  d_in[2];
    float*       out        = (float*)      d_out;

    const int B = in_sizes[1];
    const int grid = (B + BPB - 1) / BPB;
    go_feat_kernel<<<grid, NT>>>(stones, cur_player, ko_points, out, B);
}

// round 8
// speedup vs baseline: 1.1621x; 1.1621x over previous
#include <cuda_runtime.h>
#include <cstdint>

#define HH 19
#define CELLS 361
#define MASK19 0x7FFFFu
#define BPB 8
#define NT 640                // 20 warps
#define NWARP 20
#define NBITW 201             // ballot words (max idx 199) + funnel pad
#define FULLM 0xFFFFFFFFu
#define ONEF  0x3F800000u
#define TWOF  0x40000000u
#define FOURF 0x40800000u

// weak = opp stone with exactly one orthogonal opp neighbor
__device__ __forceinline__ uint32_t weak_row(uint32_t om, uint32_t ou, uint32_t od) {
    const uint32_t ol  = (om << 1) & MASK19;
    const uint32_t orr = om >> 1;
    const uint32_t par = ou ^ od ^ ol ^ orr;
    const uint32_t ge2 = (ou & od) | (ol & orr) | ((ou | od) & (ol | orr));
    return om & par & ~ge2;
}

// aligned 32-bit word w (bits [32w,32w+32)) of the 361-bit stream of 19 row masks
__device__ __forceinline__ uint32_t gather_word(const uint32_t* rm, int w) {
    uint32_t v = 0u;
    int r = (32 * w) / HH;
#pragma unroll
    for (int it = 0; it < 3; ++it) {
        if (r < HH) {
            const int sh = HH * r - 32 * w;
            if (sh < 32) {
                v |= (sh >= 0) ? (rm[r] << sh) : (rm[r] >> (-sh));
                ++r;
            }
        }
    }
    return v;
}

// bit `pos` of w as a masked float bit-pattern (no I2F)
__device__ __forceinline__ uint32_t sextbit(uint32_t w, int pos, uint32_t K) {
    return (uint32_t)(((int32_t)(w << (31 - pos))) >> 31) & K;
}

__global__ __launch_bounds__(NT, 3)
void go_feat_kernel(const float* __restrict__ stones,
                    const int*   __restrict__ cur_player,
                    const int*   __restrict__ ko_points,
                    float*       __restrict__ out,
                    int B)
{
    __shared__ uint32_t s_bits[NBITW];
    __shared__ uint32_t s_cur[BPB][23];       // pad-2 row masks (real rows at [2..20])
    __shared__ uint32_t s_opp[BPB][23];
    __shared__ uint32_t s_emp[BPB][23];
    __shared__ uint32_t s_rm[4][BPB][HH];     // 0=legal, 1=b0, 2=b1, 3=b2
    __shared__ int      s_cp[BPB];
    __shared__ float    s_turn[BPB];
    __shared__ int      s_ko[BPB][2];

    const int t     = threadIdx.x;
    const int lane  = t & 31;
    const int warp  = t >> 5;
    const int bbase = blockIdx.x * BPB;
    const int rb    = (B - bbase) < BPB ? (B - bbase) : BPB;
    const int nin   = rb * 722;

    if (t < BPB) {
        const bool ok = t < rb;
        const int  b  = bbase + (ok ? t : 0);
        const int  cp = ok ? cur_player[b] : 0;
        s_cp[t]    = cp;
        s_turn[t]  = (float)cp;
        s_ko[t][0] = ok ? ko_points[2 * b]     : -1;
        s_ko[t][1] = ok ? ko_points[2 * b + 1] : 0;
    }

    // ---- Phase A: ballot-pack input (lane-rotated for aligned LDG rows) ----
    const float* src = stones + (size_t)bbase * 722;
    const int a_in   = (int)(((size_t)bbase * 722) & 31);
    const int lrot   = (lane - a_in) & 31;    // this lane's element within each 32-chunk
#pragma unroll
    for (int k = 0; k < 10; ++k) {            // 10*640 = 6400 >= 5776
        const int e = k * NT + (warp << 5) + lrot;
        const bool act = e < nin;
        float v = 0.0f;
        if (act) v = src[e];
        const unsigned bal = __ballot_sync(FULLM, act && (v > 0.5f));
        if (lane == 0)
            s_bits[k * NWARP + warp] = __funnelshift_r(bal, bal, (unsigned)a_in);
    }
    __syncthreads();

    // ---- Phase 1: row masks ----
    if (t < BPB * HH) {
        const int lb = t / HH, r = t % HH;
        const int bit0 = lb * 722 + r * HH;
        const int bit1 = bit0 + 361;
        const uint32_t m0 = __funnelshift_r(s_bits[bit0 >> 5], s_bits[(bit0 >> 5) + 1],
                                            bit0 & 31) & MASK19;
        const uint32_t m1 = __funnelshift_r(s_bits[bit1 >> 5], s_bits[(bit1 >> 5) + 1],
                                            bit1 & 31) & MASK19;
        const int cp = s_cp[lb];
        s_cur[lb][r + 2] = cp ? m1 : m0;
        s_opp[lb][r + 2] = cp ? m0 : m1;
        s_emp[lb][r + 2] = (~(m0 | m1)) & MASK19;
        if (r == 0) {
            s_cur[lb][0] = 0u; s_cur[lb][1] = 0u; s_cur[lb][21] = 0u; s_cur[lb][22] = 0u;
            s_opp[lb][0] = 0u; s_opp[lb][1] = 0u; s_opp[lb][21] = 0u; s_opp[lb][22] = 0u;
            s_emp[lb][0] = 0u; s_emp[lb][1] = 0u; s_emp[lb][21] = 0u; s_emp[lb][22] = 0u;
        }
    }
    __syncthreads();

    // ---- Phase 3: legal row masks (weak inlined) + liberty bitplanes ----
    if (t < 2 * BPB * HH) {
        const int half = t / (BPB * HH);
        const int w    = t % (BPB * HH);
        const int lb   = w / HH, r = w % HH;
        if (half == 0) {
            const uint32_t* op = s_opp[lb];
            const uint32_t wkm = weak_row(op[r + 2], op[r + 1], op[r + 3]);
            const uint32_t wku = weak_row(op[r + 1], op[r],     op[r + 2]);
            const uint32_t wkd = weak_row(op[r + 3], op[r + 2], op[r + 4]);
            const uint32_t empb = s_emp[lb][r + 2];
            const uint32_t eu = s_emp[lb][r + 1], ed = s_emp[lb][r + 3];
            const uint32_t nbr = eu | ed | ((empb << 1) & MASK19) | (empb >> 1)
                               | wku | wkd | ((wkm << 1) & MASK19) | (wkm >> 1);
            uint32_t legal = empb & nbr;
            const int kr = s_ko[lb][0];
            if (kr >= 0) {
                const int rr = kr > (HH - 1) ? (HH - 1) : kr;
                int cc = s_ko[lb][1];
                cc = cc < 0 ? 0 : (cc > (HH - 1) ? (HH - 1) : cc);
                if (rr == r) legal &= ~(1u << cc);
            }
            s_rm[0][lb][r] = legal;
        } else {
            const uint32_t curb = s_cur[lb][r + 2];
            const uint32_t cu   = s_cur[lb][r + 1];
            const uint32_t cd   = s_cur[lb][r + 3];
            const uint32_t cl   = (curb << 1) & MASK19;
            const uint32_t crr  = curb >> 1;
            const uint32_t empb = s_emp[lb][r + 2];
            const uint32_t sab = cu ^ cd,  cab = cu & cd;
            const uint32_t scd = cl ^ crr, ccd = cl & crr;
            const uint32_t kk  = sab & scd;
            s_rm[1][lb][r] = (sab ^ scd)      & empb;
            s_rm[2][lb][r] = (cab ^ ccd ^ kk) & empb;
            s_rm[3][lb][r] = (cab & ccd)      & empb;
        }
    }
    __syncthreads();

    // ---- Phase 4: warp-per-(board,channel), lane-rotated aligned stores ----
    float* outb = out + (size_t)bbase * 1805;
#pragma unroll
    for (int u = warp; u < 5 * BPB; u += NWARP) {   // 2 units per warp
        const int lb = u / 5;
        const int ch = u - 5 * lb;
        if (lb >= rb) continue;                      // warp-uniform

        const int Grel = lb * 1805 + ch * CELLS;
        float* o = outb + Grel;
        // global alignment of this channel's base
        const int a   = (int)((((size_t)bbase * 1805) + Grel) & 31);
        const int ln2 = (lane - a) & 31;             // loop-invariant per unit

        if (ch == 4) {
            const float tv = s_turn[lb];
#pragma unroll
            for (int it = 0; it < 12; ++it) {
                const int idx = it * 32 + ln2;
                if (idx < CELLS) o[idx] = tv;
            }
        } else if (ch == 3) {
            uint32_t w0 = 0u, w1 = 0u, w2 = 0u;
            if (lane < 12) {
                w0 = gather_word(s_rm[1][lb], lane);
                w1 = gather_word(s_rm[2][lb], lane);
                w2 = gather_word(s_rm[3][lb], lane);
            }
#pragma unroll
            for (int it = 0; it < 12; ++it) {
                const uint32_t aw = __shfl_sync(FULLM, w0, it);
                const uint32_t bw = __shfl_sync(FULLM, w1, it);
                const uint32_t cw = __shfl_sync(FULLM, w2, it);
                const int idx = it * 32 + ln2;
                const float f = __uint_as_float(sextbit(aw, ln2, ONEF))
                              + __uint_as_float(sextbit(bw, ln2, TWOF))
                              + __uint_as_float(sextbit(cw, ln2, FOURF));
                if (idx < CELLS) o[idx] = f;
            }
        } else {
            uint32_t myw = 0u;
            if (lane < 12) {
                if (ch == 2) {
                    myw = gather_word(s_rm[0][lb], lane);
                } else {
                    const int pl   = (ch == 0) ? s_cp[lb] : 1 - s_cp[lb];
                    const int base = lb * 722 + pl * CELLS + 32 * lane;
                    myw = __funnelshift_r(s_bits[base >> 5], s_bits[(base >> 5) + 1],
                                          base & 31);
                }
            }
#pragma unroll
            for (int it = 0; it < 12; ++it) {
                const uint32_t w = __shfl_sync(FULLM, myw, it);
                const int idx = it * 32 + ln2;
                if (idx < CELLS)
                    o[idx] = __uint_as_float(sextbit(w, ln2, ONEF));
            }
        }
    }
}

extern "C" void kernel_launch(void* const* d_in, const int* in_sizes, int n_in,
                              void* d_out, int out_size)
{
    const float* stones     = (const float*)d_in[0];
    const int*   cur_player = (const int*)  d_in[1];
    const int*   ko_points  = (const int*)  d_in[2];
    float*       out        = (float*)      d_out;

    const int B = in_sizes[1];
    const int grid = (B + BPB - 1) / BPB;
    go_feat_kernel<<<grid, NT>>>(stones, cur_player, ko_points, out, B);
}